// round 16
// baseline (speedup 1.0000x reference)
#include <cuda_runtime.h>
#include <cuda_bf16.h>
#include <cstdint>

// ============================================================================
// ECE over N=2^24, 15 bins — bulk-async (UBLKCP) pipeline + register
// threshold accumulators. R16 = R15 scaled to 3 CTAs/SM.
//
//   U_k = sum_i (c_i - a_i) * [c_i*nb > k],  k=0..14;  S_b = U_b - U_{b+1}
//   ece = sum_{b<nb} |S_b| / n     (self-gating, bit-exact vs ceil binning)
//
// R15 result: cp.async.bulk removed the L1tex load-queue wall (issue 74%,
// alu 50% at just 16 warps/SM). Now issue-capacity-bound -> add warps:
// grid 444 = 3 CTAs/SM (64KB dyn smem each, 192KB < 228KB carveout).
// Pipe budget at 3 elem/cyc/SM: alu 75%, fma 80%, issue 87% -> DRAM binds.
// ============================================================================

#define TPB 256
#define STAGE_ELEMS 2048
#define STAGE_BYTES (STAGE_ELEMS * 4)
#define NSTAGE 4
#define NBLOCKS 444            // 3 CTAs/SM * 148 SMs
#define NBINS 15
#define BSTRIDE 16
#define MAX_BLOCKS 4096

__device__ float g_partial[MAX_BLOCKS * BSTRIDE];
__device__ unsigned int g_count = 0;

__device__ __forceinline__ uint32_t smem_u32(const void* p) {
    uint32_t r;
    asm("{ .reg .u64 t; cvta.to.shared.u64 t, %1; cvt.u32.u64 %0, t; }"
        : "=r"(r) : "l"(p));
    return r;
}

__device__ __forceinline__ void mbar_init(uint32_t mbar, uint32_t cnt) {
    asm volatile("mbarrier.init.shared.b64 [%0], %1;" :: "r"(mbar), "r"(cnt) : "memory");
}
__device__ __forceinline__ void mbar_expect_tx(uint32_t mbar, uint32_t bytes) {
    asm volatile("mbarrier.arrive.expect_tx.shared.b64 _, [%0], %1;"
                 :: "r"(mbar), "r"(bytes) : "memory");
}
__device__ __forceinline__ void mbar_wait(uint32_t mbar, uint32_t parity) {
    uint32_t done;
    asm volatile(
        "{\n\t.reg .pred p;\n\t"
        "mbarrier.try_wait.parity.acquire.cta.shared::cta.b64 p, [%1], %2;\n\t"
        "selp.b32 %0, 1, 0, p;\n\t}"
        : "=r"(done) : "r"(mbar), "r"(parity) : "memory");
    if (!done) {
        asm volatile(
            "{\n\t.reg .pred P1;\n\t"
            "W_%=:\n\t"
            "mbarrier.try_wait.parity.acquire.cta.shared::cta.b64 P1, [%0], %1, 0x989680;\n\t"
            "@P1 bra.uni D_%=;\n\t"
            "bra.uni W_%=;\n\t"
            "D_%=:\n\t}"
            :: "r"(mbar), "r"(parity) : "memory");
    }
}
__device__ __forceinline__ void bulk_ld(uint32_t dst_smem, const void* src,
                                        uint32_t bytes, uint32_t mbar) {
    asm volatile(
        "cp.async.bulk.shared::cluster.global.mbarrier::complete_tx::bytes "
        "[%0], [%1], %2, [%3];"
        :: "r"(dst_smem), "l"(src), "r"(bytes), "r"(mbar) : "memory");
}

// x = c*nb, d = c - a. A[k] += d for every k with x > k.
__device__ __forceinline__ void accum15(float x, float d, float* A) {
    asm("{\n\t"
        ".reg .pred p0,p1,p2,p3,p4,p5,p6,p7,p8,p9,p10,p11,p12,p13,p14;\n\t"
        "setp.gt.f32 p0,  %15, 0f00000000;\n\t"
        "setp.gt.f32 p1,  %15, 0f3F800000;\n\t"
        "setp.gt.f32 p2,  %15, 0f40000000;\n\t"
        "setp.gt.f32 p3,  %15, 0f40400000;\n\t"
        "setp.gt.f32 p4,  %15, 0f40800000;\n\t"
        "setp.gt.f32 p5,  %15, 0f40A00000;\n\t"
        "setp.gt.f32 p6,  %15, 0f40C00000;\n\t"
        "setp.gt.f32 p7,  %15, 0f40E00000;\n\t"
        "setp.gt.f32 p8,  %15, 0f41000000;\n\t"
        "setp.gt.f32 p9,  %15, 0f41100000;\n\t"
        "setp.gt.f32 p10, %15, 0f41200000;\n\t"
        "setp.gt.f32 p11, %15, 0f41300000;\n\t"
        "setp.gt.f32 p12, %15, 0f41400000;\n\t"
        "setp.gt.f32 p13, %15, 0f41500000;\n\t"
        "setp.gt.f32 p14, %15, 0f41600000;\n\t"
        "@p0  add.f32 %0,  %0,  %16;\n\t"
        "@p1  add.f32 %1,  %1,  %16;\n\t"
        "@p2  add.f32 %2,  %2,  %16;\n\t"
        "@p3  add.f32 %3,  %3,  %16;\n\t"
        "@p4  add.f32 %4,  %4,  %16;\n\t"
        "@p5  add.f32 %5,  %5,  %16;\n\t"
        "@p6  add.f32 %6,  %6,  %16;\n\t"
        "@p7  add.f32 %7,  %7,  %16;\n\t"
        "@p8  add.f32 %8,  %8,  %16;\n\t"
        "@p9  add.f32 %9,  %9,  %16;\n\t"
        "@p10 add.f32 %10, %10, %16;\n\t"
        "@p11 add.f32 %11, %11, %16;\n\t"
        "@p12 add.f32 %12, %12, %16;\n\t"
        "@p13 add.f32 %13, %13, %16;\n\t"
        "@p14 add.f32 %14, %14, %16;\n\t"
        "}"
        : "+f"(A[0]), "+f"(A[1]), "+f"(A[2]), "+f"(A[3]), "+f"(A[4]),
          "+f"(A[5]), "+f"(A[6]), "+f"(A[7]), "+f"(A[8]), "+f"(A[9]),
          "+f"(A[10]), "+f"(A[11]), "+f"(A[12]), "+f"(A[13]), "+f"(A[14])
        : "f"(x), "f"(d));
}

__global__ __launch_bounds__(TPB, 3)
void ece_kernel(const float* __restrict__ conf,
                const float* __restrict__ ac,
                const int* __restrict__ num_bins_p,
                int n,
                float* __restrict__ out) {
    // dynamic smem: [ c stages | a stages ]  (NSTAGE * 8KB each = 64 KB)
    extern __shared__ float dyn[];
    float* sm_c = dyn;
    float* sm_a = dyn + NSTAGE * STAGE_ELEMS;

    __shared__ unsigned long long mbar_s[NSTAGE];
    __shared__ float red[8 * BSTRIDE];
    __shared__ bool is_last;

    const int tid = threadIdx.x;
    const int wid = tid >> 5;
    const int lane = tid & 31;
    const int bid = blockIdx.x;
    const int nb = *num_bins_p;            // valid for nb <= 15
    const float fnb = (float)nb;

    const uint32_t mb0 = smem_u32(&mbar_s[0]);

    if (tid == 0) {
        #pragma unroll
        for (int q = 0; q < NSTAGE; q++)
            mbar_init(mb0 + q * 8, 1);
    }
    __syncthreads();

    const int full_stages = n >> 11;       // 8192 for n = 2^24

    // prologue: issue first NSTAGE stages
    if (tid == 0) {
        #pragma unroll
        for (int q = 0; q < NSTAGE; q++) {
            int s = bid + q * NBLOCKS;
            if (s < full_stages) {
                uint32_t mb = mb0 + q * 8;
                mbar_expect_tx(mb, 2 * STAGE_BYTES);
                bulk_ld(smem_u32(sm_c + q * STAGE_ELEMS),
                        conf + (size_t)s * STAGE_ELEMS, STAGE_BYTES, mb);
                bulk_ld(smem_u32(sm_a + q * STAGE_ELEMS),
                        ac + (size_t)s * STAGE_ELEMS, STAGE_BYTES, mb);
            }
        }
    }

    float A[NBINS];
    #pragma unroll
    for (int k = 0; k < NBINS; k++) A[k] = 0.0f;

    int it = 0;
    for (int s = bid; s < full_stages; s += NBLOCKS, it++) {
        const int buf = it & (NSTAGE - 1);
        const uint32_t ph = (uint32_t)((it >> 2) & 1);
        mbar_wait(mb0 + buf * 8, ph);

        const float4* sc = (const float4*)(sm_c + buf * STAGE_ELEMS);
        const float4* sa = (const float4*)(sm_a + buf * STAGE_ELEMS);
        const float4 c0 = sc[tid];
        const float4 c1 = sc[tid + TPB];
        const float4 a0 = sa[tid];
        const float4 a1 = sa[tid + TPB];
        accum15(c0.x * fnb, c0.x - a0.x, A);
        accum15(c0.y * fnb, c0.y - a0.y, A);
        accum15(c0.z * fnb, c0.z - a0.z, A);
        accum15(c0.w * fnb, c0.w - a0.w, A);
        accum15(c1.x * fnb, c1.x - a1.x, A);
        accum15(c1.y * fnb, c1.y - a1.y, A);
        accum15(c1.z * fnb, c1.z - a1.z, A);
        accum15(c1.w * fnb, c1.w - a1.w, A);

        __syncthreads();                   // all consumed -> buf reusable
        const int nxt = s + NSTAGE * NBLOCKS;
        if (tid == 0 && nxt < full_stages) {
            uint32_t mb = mb0 + buf * 8;
            mbar_expect_tx(mb, 2 * STAGE_BYTES);
            bulk_ld(smem_u32(sm_c + buf * STAGE_ELEMS),
                    conf + (size_t)nxt * STAGE_ELEMS, STAGE_BYTES, mb);
            bulk_ld(smem_u32(sm_a + buf * STAGE_ELEMS),
                    ac + (size_t)nxt * STAGE_ELEMS, STAGE_BYTES, mb);
        }
    }

    // remainder elements (n not multiple of 2048): block 0, direct LDG
    if (bid == 0) {
        for (int j = (full_stages << 11) + tid; j < n; j += TPB) {
            const float cf = conf[j];
            accum15(cf * fnb, cf - ac[j], A);
        }
    }

    // ---- warp shfl-reduce, then cross-warp ----
    #pragma unroll
    for (int k = 0; k < NBINS; k++) {
        float v = A[k];
        #pragma unroll
        for (int off = 16; off > 0; off >>= 1)
            v += __shfl_xor_sync(0xffffffffu, v, off);
        if (lane == 0) red[wid * BSTRIDE + k] = v;
    }
    __syncthreads();

    if (tid < BSTRIDE) {
        float t = 0.0f;
        #pragma unroll
        for (int w = 0; w < TPB / 32; w++)
            t += (tid < NBINS) ? red[w * BSTRIDE + tid] : 0.0f;
        g_partial[bid * BSTRIDE + tid] = (tid < NBINS) ? t : 0.0f;
    }

    // ---- last-block tail reduction (no second launch) ----
    __threadfence();
    if (tid == 0) {
        unsigned int ticket = atomicAdd(&g_count, 1u);
        is_last = (ticket == gridDim.x - 1);
    }
    __syncthreads();

    if (is_last) {
        __threadfence();
        const int total = gridDim.x * BSTRIDE;
        float sacc = 0.0f;
        for (int e = tid; e < total; e += TPB)    // slot = e & 15 fixed
            sacc += g_partial[e];

        __shared__ float r2[TPB];
        r2[tid] = sacc;
        __syncthreads();

        __shared__ float U[BSTRIDE];
        if (tid < BSTRIDE) {
            float t = 0.0f;
            #pragma unroll
            for (int k = 0; k < TPB / BSTRIDE; k++)
                t += r2[tid + k * BSTRIDE];
            U[tid] = t;                           // U[15] = 0 automatically
        }
        __syncthreads();

        if (tid == 0) {
            float tot = 0.0f;
            for (int b = 0; b < nb; b++)          // S_b = U_b - U_{b+1}
                tot += fabsf(U[b] - U[b + 1]);
            out[0] = tot / (float)n;
            g_count = 0;                          // reset for next replay
        }
    }
}

extern "C" void kernel_launch(void* const* d_in, const int* in_sizes, int n_in,
                              void* d_out, int out_size) {
    const float* conf = (const float*)d_in[0];
    const float* acc  = (const float*)d_in[1];
    const int*   nbp  = (const int*)d_in[2];
    float* out = (float*)d_out;
    const int n = in_sizes[0];

    const int dyn_bytes = NSTAGE * STAGE_BYTES * 2;   // 64 KB
    cudaFuncSetAttribute(ece_kernel,
                         cudaFuncAttributeMaxDynamicSharedMemorySize, dyn_bytes);
    ece_kernel<<<NBLOCKS, TPB, dyn_bytes>>>(conf, acc, nbp, n, out);
}

// round 17
// speedup vs baseline: 1.0569x; 1.0569x over previous
#include <cuda_runtime.h>
#include <cuda_bf16.h>
#include <cstdint>

// ============================================================================
// ECE over N=2^24, 15 bins — bulk-async (UBLKCP) pipeline + register
// threshold accumulators. R17 = R16 scaled to 4 CTAs/SM (NSTAGE 4 -> 3).
//
//   U_k = sum_i (c_i - a_i) * [c_i*nb > k],  k=0..14;  S_b = U_b - U_{b+1}
//   ece = sum_{b<nb} |S_b| / n     (self-gating, bit-exact vs ceil binning)
//
// Scaling ledger: 16 warps/SM -> 31.3us, 24 -> 28.8us (DRAM 61%, issue 76%,
// alu 52% — nothing saturated). 32 warps/SM via 48KB smem/CTA (3-stage ring,
// 192KB/SM < 228KB carveout), grid 592 = 4*148 exact.
// ============================================================================

#define TPB 256
#define STAGE_ELEMS 2048
#define STAGE_BYTES (STAGE_ELEMS * 4)
#define NSTAGE 3
#define NBLOCKS 592            // 4 CTAs/SM * 148 SMs
#define NBINS 15
#define BSTRIDE 16
#define MAX_BLOCKS 4096

__device__ float g_partial[MAX_BLOCKS * BSTRIDE];
__device__ unsigned int g_count = 0;

__device__ __forceinline__ uint32_t smem_u32(const void* p) {
    uint32_t r;
    asm("{ .reg .u64 t; cvta.to.shared.u64 t, %1; cvt.u32.u64 %0, t; }"
        : "=r"(r) : "l"(p));
    return r;
}

__device__ __forceinline__ void mbar_init(uint32_t mbar, uint32_t cnt) {
    asm volatile("mbarrier.init.shared.b64 [%0], %1;" :: "r"(mbar), "r"(cnt) : "memory");
}
__device__ __forceinline__ void mbar_expect_tx(uint32_t mbar, uint32_t bytes) {
    asm volatile("mbarrier.arrive.expect_tx.shared.b64 _, [%0], %1;"
                 :: "r"(mbar), "r"(bytes) : "memory");
}
__device__ __forceinline__ void mbar_wait(uint32_t mbar, uint32_t parity) {
    uint32_t done;
    asm volatile(
        "{\n\t.reg .pred p;\n\t"
        "mbarrier.try_wait.parity.acquire.cta.shared::cta.b64 p, [%1], %2;\n\t"
        "selp.b32 %0, 1, 0, p;\n\t}"
        : "=r"(done) : "r"(mbar), "r"(parity) : "memory");
    if (!done) {
        asm volatile(
            "{\n\t.reg .pred P1;\n\t"
            "W_%=:\n\t"
            "mbarrier.try_wait.parity.acquire.cta.shared::cta.b64 P1, [%0], %1, 0x989680;\n\t"
            "@P1 bra.uni D_%=;\n\t"
            "bra.uni W_%=;\n\t"
            "D_%=:\n\t}"
            :: "r"(mbar), "r"(parity) : "memory");
    }
}
__device__ __forceinline__ void bulk_ld(uint32_t dst_smem, const void* src,
                                        uint32_t bytes, uint32_t mbar) {
    asm volatile(
        "cp.async.bulk.shared::cluster.global.mbarrier::complete_tx::bytes "
        "[%0], [%1], %2, [%3];"
        :: "r"(dst_smem), "l"(src), "r"(bytes), "r"(mbar) : "memory");
}

// x = c*nb, d = c - a. A[k] += d for every k with x > k.
__device__ __forceinline__ void accum15(float x, float d, float* A) {
    asm("{\n\t"
        ".reg .pred p0,p1,p2,p3,p4,p5,p6,p7,p8,p9,p10,p11,p12,p13,p14;\n\t"
        "setp.gt.f32 p0,  %15, 0f00000000;\n\t"
        "setp.gt.f32 p1,  %15, 0f3F800000;\n\t"
        "setp.gt.f32 p2,  %15, 0f40000000;\n\t"
        "setp.gt.f32 p3,  %15, 0f40400000;\n\t"
        "setp.gt.f32 p4,  %15, 0f40800000;\n\t"
        "setp.gt.f32 p5,  %15, 0f40A00000;\n\t"
        "setp.gt.f32 p6,  %15, 0f40C00000;\n\t"
        "setp.gt.f32 p7,  %15, 0f40E00000;\n\t"
        "setp.gt.f32 p8,  %15, 0f41000000;\n\t"
        "setp.gt.f32 p9,  %15, 0f41100000;\n\t"
        "setp.gt.f32 p10, %15, 0f41200000;\n\t"
        "setp.gt.f32 p11, %15, 0f41300000;\n\t"
        "setp.gt.f32 p12, %15, 0f41400000;\n\t"
        "setp.gt.f32 p13, %15, 0f41500000;\n\t"
        "setp.gt.f32 p14, %15, 0f41600000;\n\t"
        "@p0  add.f32 %0,  %0,  %16;\n\t"
        "@p1  add.f32 %1,  %1,  %16;\n\t"
        "@p2  add.f32 %2,  %2,  %16;\n\t"
        "@p3  add.f32 %3,  %3,  %16;\n\t"
        "@p4  add.f32 %4,  %4,  %16;\n\t"
        "@p5  add.f32 %5,  %5,  %16;\n\t"
        "@p6  add.f32 %6,  %6,  %16;\n\t"
        "@p7  add.f32 %7,  %7,  %16;\n\t"
        "@p8  add.f32 %8,  %8,  %16;\n\t"
        "@p9  add.f32 %9,  %9,  %16;\n\t"
        "@p10 add.f32 %10, %10, %16;\n\t"
        "@p11 add.f32 %11, %11, %16;\n\t"
        "@p12 add.f32 %12, %12, %16;\n\t"
        "@p13 add.f32 %13, %13, %16;\n\t"
        "@p14 add.f32 %14, %14, %16;\n\t"
        "}"
        : "+f"(A[0]), "+f"(A[1]), "+f"(A[2]), "+f"(A[3]), "+f"(A[4]),
          "+f"(A[5]), "+f"(A[6]), "+f"(A[7]), "+f"(A[8]), "+f"(A[9]),
          "+f"(A[10]), "+f"(A[11]), "+f"(A[12]), "+f"(A[13]), "+f"(A[14])
        : "f"(x), "f"(d));
}

__global__ __launch_bounds__(TPB, 4)
void ece_kernel(const float* __restrict__ conf,
                const float* __restrict__ ac,
                const int* __restrict__ num_bins_p,
                int n,
                float* __restrict__ out) {
    // dynamic smem: [ c stages | a stages ]  (NSTAGE * 8KB each = 48 KB)
    extern __shared__ float dyn[];
    float* sm_c = dyn;
    float* sm_a = dyn + NSTAGE * STAGE_ELEMS;

    __shared__ unsigned long long mbar_s[NSTAGE];
    __shared__ float red[8 * BSTRIDE];
    __shared__ bool is_last;

    const int tid = threadIdx.x;
    const int wid = tid >> 5;
    const int lane = tid & 31;
    const int bid = blockIdx.x;
    const int nb = *num_bins_p;            // valid for nb <= 15
    const float fnb = (float)nb;

    const uint32_t mb0 = smem_u32(&mbar_s[0]);

    if (tid == 0) {
        #pragma unroll
        for (int q = 0; q < NSTAGE; q++)
            mbar_init(mb0 + q * 8, 1);
    }
    __syncthreads();

    const int full_stages = n >> 11;       // 8192 for n = 2^24

    // prologue: issue first NSTAGE stages
    if (tid == 0) {
        #pragma unroll
        for (int q = 0; q < NSTAGE; q++) {
            int s = bid + q * NBLOCKS;
            if (s < full_stages) {
                uint32_t mb = mb0 + q * 8;
                mbar_expect_tx(mb, 2 * STAGE_BYTES);
                bulk_ld(smem_u32(sm_c + q * STAGE_ELEMS),
                        conf + (size_t)s * STAGE_ELEMS, STAGE_BYTES, mb);
                bulk_ld(smem_u32(sm_a + q * STAGE_ELEMS),
                        ac + (size_t)s * STAGE_ELEMS, STAGE_BYTES, mb);
            }
        }
    }

    float A[NBINS];
    #pragma unroll
    for (int k = 0; k < NBINS; k++) A[k] = 0.0f;

    int buf = 0;
    uint32_t ph = 0;
    for (int s = bid; s < full_stages; s += NBLOCKS) {
        mbar_wait(mb0 + buf * 8, ph);

        const float4* sc = (const float4*)(sm_c + buf * STAGE_ELEMS);
        const float4* sa = (const float4*)(sm_a + buf * STAGE_ELEMS);
        const float4 c0 = sc[tid];
        const float4 c1 = sc[tid + TPB];
        const float4 a0 = sa[tid];
        const float4 a1 = sa[tid + TPB];
        accum15(c0.x * fnb, c0.x - a0.x, A);
        accum15(c0.y * fnb, c0.y - a0.y, A);
        accum15(c0.z * fnb, c0.z - a0.z, A);
        accum15(c0.w * fnb, c0.w - a0.w, A);
        accum15(c1.x * fnb, c1.x - a1.x, A);
        accum15(c1.y * fnb, c1.y - a1.y, A);
        accum15(c1.z * fnb, c1.z - a1.z, A);
        accum15(c1.w * fnb, c1.w - a1.w, A);

        __syncthreads();                   // all consumed -> buf reusable
        const int nxt = s + NSTAGE * NBLOCKS;
        if (tid == 0 && nxt < full_stages) {
            uint32_t mb = mb0 + buf * 8;
            mbar_expect_tx(mb, 2 * STAGE_BYTES);
            bulk_ld(smem_u32(sm_c + buf * STAGE_ELEMS),
                    conf + (size_t)nxt * STAGE_ELEMS, STAGE_BYTES, mb);
            bulk_ld(smem_u32(sm_a + buf * STAGE_ELEMS),
                    ac + (size_t)nxt * STAGE_ELEMS, STAGE_BYTES, mb);
        }
        if (++buf == NSTAGE) { buf = 0; ph ^= 1; }
    }

    // remainder elements (n not multiple of 2048): block 0, direct LDG
    if (bid == 0) {
        for (int j = (full_stages << 11) + tid; j < n; j += TPB) {
            const float cf = conf[j];
            accum15(cf * fnb, cf - ac[j], A);
        }
    }

    // ---- warp shfl-reduce, then cross-warp ----
    #pragma unroll
    for (int k = 0; k < NBINS; k++) {
        float v = A[k];
        #pragma unroll
        for (int off = 16; off > 0; off >>= 1)
            v += __shfl_xor_sync(0xffffffffu, v, off);
        if (lane == 0) red[wid * BSTRIDE + k] = v;
    }
    __syncthreads();

    if (tid < BSTRIDE) {
        float t = 0.0f;
        #pragma unroll
        for (int w = 0; w < TPB / 32; w++)
            t += (tid < NBINS) ? red[w * BSTRIDE + tid] : 0.0f;
        g_partial[bid * BSTRIDE + tid] = (tid < NBINS) ? t : 0.0f;
    }

    // ---- last-block tail reduction (no second launch) ----
    __threadfence();
    if (tid == 0) {
        unsigned int ticket = atomicAdd(&g_count, 1u);
        is_last = (ticket == gridDim.x - 1);
    }
    __syncthreads();

    if (is_last) {
        __threadfence();
        const int total = gridDim.x * BSTRIDE;
        float sacc = 0.0f;
        for (int e = tid; e < total; e += TPB)    // slot = e & 15 fixed
            sacc += g_partial[e];

        __shared__ float r2[TPB];
        r2[tid] = sacc;
        __syncthreads();

        __shared__ float U[BSTRIDE];
        if (tid < BSTRIDE) {
            float t = 0.0f;
            #pragma unroll
            for (int k = 0; k < TPB / BSTRIDE; k++)
                t += r2[tid + k * BSTRIDE];
            U[tid] = t;                           // U[15] = 0 automatically
        }
        __syncthreads();

        if (tid == 0) {
            float tot = 0.0f;
            for (int b = 0; b < nb; b++)          // S_b = U_b - U_{b+1}
                tot += fabsf(U[b] - U[b + 1]);
            out[0] = tot / (float)n;
            g_count = 0;                          // reset for next replay
        }
    }
}

extern "C" void kernel_launch(void* const* d_in, const int* in_sizes, int n_in,
                              void* d_out, int out_size) {
    const float* conf = (const float*)d_in[0];
    const float* acc  = (const float*)d_in[1];
    const int*   nbp  = (const int*)d_in[2];
    float* out = (float*)d_out;
    const int n = in_sizes[0];

    const int dyn_bytes = NSTAGE * STAGE_BYTES * 2;   // 48 KB
    cudaFuncSetAttribute(ece_kernel,
                         cudaFuncAttributeMaxDynamicSharedMemorySize, dyn_bytes);
    ece_kernel<<<NBLOCKS, TPB, dyn_bytes>>>(conf, acc, nbp, n, out);
}